// round 8
// baseline (speedup 1.0000x reference)
#include <cuda_runtime.h>
#include <math.h>

// Problem constants
#define BB 4
#define TT 2048
#define CC 1024
#define HH 16
#define HD 64
#define M_ROWS (BB * TT)       // 8192
#define N3 (3 * CC)            // 3072

// Scratch (device globals -- allocation API is forbidden)
__device__ float g_qkv[(size_t)M_ROWS * N3];     // 100.7 MB
__device__ float g_attn[(size_t)M_ROWS * CC];    // 33.6 MB

// ---------------------------------------------------------------------------
// Helpers
// ---------------------------------------------------------------------------
__device__ __forceinline__ unsigned f2tf32(float x) {
    unsigned r;
    asm("cvt.rna.tf32.f32 %0, %1;" : "=r"(r) : "f"(x));
    return r;
}
__device__ __forceinline__ float ex2f(float x) {
    float r;
    asm("ex2.approx.ftz.f32 %0, %1;" : "=f"(r) : "f"(x));
    return r;
}
__device__ __forceinline__ void mma_tf32(float* d, const unsigned* a, const unsigned* b) {
    asm volatile(
        "mma.sync.aligned.m16n8k8.row.col.f32.tf32.tf32.f32 "
        "{%0,%1,%2,%3}, {%4,%5,%6,%7}, {%8,%9}, {%0,%1,%2,%3};"
        : "+f"(d[0]), "+f"(d[1]), "+f"(d[2]), "+f"(d[3])
        : "r"(a[0]), "r"(a[1]), "r"(a[2]), "r"(a[3]), "r"(b[0]), "r"(b[1]));
}

extern __shared__ unsigned dynsm_u[];

// ---------------------------------------------------------------------------
// tf32 tensor GEMM. C[M,N] = A[M,K] @ B[K,N], row-major. M%128, N%128, K%32.
// CTA 128x128, BK=32, 256 threads, 8 warps 2(M)x4(N), warp tile 64x32.
// 3-stage smem pipeline, register-staged LDG 2 tiles ahead, tf32 cvt at
// staging (once per element).
//   A staged PERMUTED: As[m][pk(k)], pk(k)=(k%4)*8+k/4, stride 36
//       -> fragment pair (k, k+4) adjacent -> LDS.64 loads.
//   B staged k-major:  Bs[k][n], stride 136 (STS.128 staging conflict-free,
//       LDS.32 frag loads conflict-free).
// ---------------------------------------------------------------------------
#define GAS 36
#define GBS 136
#define G_A_WORDS (128 * GAS)          // 4608
#define G_B_WORDS (32 * GBS)           // 4352
#define G_STG (G_A_WORDS + G_B_WORDS)  // 8960
#define GEMM_SMEM_BYTES (3 * G_STG * 4)   // 107520

__global__ __launch_bounds__(256, 2)
void gemm_tf32(const float* __restrict__ A, const float* __restrict__ B,
               float* __restrict__ C, int M, int N, int K)
{
    const int tid  = threadIdx.x;
    const int lane = tid & 31;
    const int wid  = tid >> 5;
    const int gid  = lane >> 2;
    const int tig  = lane & 3;
    const int wm   = wid >> 2;     // 0..1 -> M
    const int wn   = wid & 3;      // 0..3 -> N
    const int bM   = blockIdx.y * 128;
    const int bN   = blockIdx.x * 128;

    float4 rA[4], rB[4];

    // A: idx = tid + r*256 -> row 0..127, c4 = idx&7 (col = 4*c4)
    // B: idx = tid + r*256 -> row 0..31,  col = (idx&31)*4
    auto ldg = [&](int kb) {
        #pragma unroll
        for (int r = 0; r < 4; r++) {
            int idx = tid + r * 256;
            rA[r] = *(const float4*)(A + (size_t)(bM + (idx >> 3)) * K + kb + (idx & 7) * 4);
        }
        #pragma unroll
        for (int r = 0; r < 4; r++) {
            int idx = tid + r * 256;
            rB[r] = *(const float4*)(B + (size_t)(kb + (idx >> 5)) * N + bN + (idx & 31) * 4);
        }
    };
    auto sts = [&](int s) {
        unsigned* As = dynsm_u + s * G_STG;
        unsigned* Bs = As + G_A_WORDS;
        #pragma unroll
        for (int r = 0; r < 4; r++) {
            int idx = tid + r * 256;
            unsigned* p = As + (idx >> 3) * GAS + (idx & 7);
            p[0]  = f2tf32(rA[r].x);
            p[8]  = f2tf32(rA[r].y);
            p[16] = f2tf32(rA[r].z);
            p[24] = f2tf32(rA[r].w);
        }
        #pragma unroll
        for (int r = 0; r < 4; r++) {
            int idx = tid + r * 256;
            uint4 t = make_uint4(f2tf32(rB[r].x), f2tf32(rB[r].y),
                                 f2tf32(rB[r].z), f2tf32(rB[r].w));
            *(uint4*)&Bs[(idx >> 5) * GBS + (idx & 31) * 4] = t;
        }
    };

    float acc[4][4][4];
    #pragma unroll
    for (int mi = 0; mi < 4; mi++)
        #pragma unroll
        for (int nj = 0; nj < 4; nj++)
            #pragma unroll
            for (int e = 0; e < 4; e++) acc[mi][nj][e] = 0.0f;

    const int ntile = K >> 5;
    ldg(0);
    sts(0);
    ldg(32);

    for (int i = 0; i < ntile; i++) {
        if (i + 1 < ntile) sts((i + 1) % 3);
        if (i + 2 < ntile) ldg((i + 2) * 32);
        __syncthreads();

        const unsigned* As = dynsm_u + (i % 3) * G_STG;
        const unsigned* Bs = As + G_A_WORDS;

        #pragma unroll
        for (int ks = 0; ks < 4; ks++) {
            const int off = tig * 8 + 2 * ks;
            unsigned af[4][4], bf[4][2];
            #pragma unroll
            for (int mi = 0; mi < 4; mi++) {
                int m = wm * 64 + mi * 16 + gid;
                uint2 q0 = *(const uint2*)&As[m * GAS + off];
                uint2 q1 = *(const uint2*)&As[(m + 8) * GAS + off];
                af[mi][0] = q0.x; af[mi][1] = q1.x; af[mi][2] = q0.y; af[mi][3] = q1.y;
            }
            #pragma unroll
            for (int nj = 0; nj < 4; nj++) {
                int n = wn * 32 + nj * 8 + gid;
                int k = ks * 8 + tig;
                bf[nj][0] = Bs[k * GBS + n];
                bf[nj][1] = Bs[(k + 4) * GBS + n];
            }
            #pragma unroll
            for (int mi = 0; mi < 4; mi++)
                #pragma unroll
                for (int nj = 0; nj < 4; nj++)
                    mma_tf32(acc[mi][nj], af[mi], bf[nj]);
        }
    }

    // Epilogue
    #pragma unroll
    for (int mi = 0; mi < 4; mi++) {
        #pragma unroll
        for (int nj = 0; nj < 4; nj++) {
            int row = bM + wm * 64 + mi * 16 + gid;
            int col = bN + wn * 32 + nj * 8 + 2 * tig;
            *(float2*)(C + (size_t)row * N + col) =
                make_float2(acc[mi][nj][0], acc[mi][nj][1]);
            *(float2*)(C + (size_t)(row + 8) * N + col) =
                make_float2(acc[mi][nj][2], acc[mi][nj][3]);
        }
    }
}

// ---------------------------------------------------------------------------
// Tensor-core flash attention (causal, tf32 mma, fp32 accum). R2/R6 version.
// CTA: 128 query rows, 4 warps x 32 rows. 64-key tiles.
// ---------------------------------------------------------------------------
#define QS 68
#define KSS 68
#define VSS 72
#define ATT_SMEM_FLOATS (128 * QS + 64 * KSS + 64 * VSS)   // 17664
#define ATT_SMEM_BYTES  (ATT_SMEM_FLOATS * 4)              // 70656

__global__ __launch_bounds__(128)
void attn_tc()
{
    unsigned* Qs  = dynsm_u;
    unsigned* Ksm = dynsm_u + 128 * QS;
    unsigned* Vsm = Ksm + 64 * KSS;

    const int tid  = threadIdx.x;
    const int lane = tid & 31;
    const int w    = tid >> 5;
    const int gid  = lane >> 2;
    const int tig  = lane & 3;
    const int qt   = blockIdx.x;
    const int bh   = blockIdx.y;
    const int b    = bh >> 4;
    const int h    = bh & 15;

    const float* base = g_qkv + (size_t)b * TT * N3;
    const float qscale = 0.125f * 1.44269504f;   // 1/sqrt(64) * log2(e)

    #pragma unroll
    for (int r = 0; r < 16; r++) {
        int idx = tid + r * 128;
        int row = idx >> 4;
        int c   = (idx & 15) * 4;
        float4 v = *(const float4*)(base + (size_t)(qt * 128 + row) * N3 + h * HD + c);
        uint4 t = make_uint4(f2tf32(v.x * qscale), f2tf32(v.y * qscale),
                             f2tf32(v.z * qscale), f2tf32(v.w * qscale));
        *(uint4*)&Qs[row * QS + c] = t;
    }

    float o[2][8][4];
    #pragma unroll
    for (int mi = 0; mi < 2; mi++)
        #pragma unroll
        for (int nj = 0; nj < 8; nj++)
            #pragma unroll
            for (int e = 0; e < 4; e++) o[mi][nj][e] = 0.0f;
    float mst[4] = {-1e30f, -1e30f, -1e30f, -1e30f};
    float lst[4] = {0.f, 0.f, 0.f, 0.f};

    const int ntiles = 2 * qt + 2;

    for (int kt = 0; kt < ntiles; kt++) {
        __syncthreads();
        const float* kb_ = base + (size_t)(kt * 64) * N3 + CC + h * HD;
        const float* vb_ = base + (size_t)(kt * 64) * N3 + 2 * CC + h * HD;
        #pragma unroll
        for (int r = 0; r < 8; r++) {
            int idx = tid + r * 128;
            int row = idx >> 4;
            int c   = (idx & 15) * 4;
            float4 kv = *(const float4*)(kb_ + (size_t)row * N3 + c);
            float4 vv = *(const float4*)(vb_ + (size_t)row * N3 + c);
            *(uint4*)&Ksm[row * KSS + c] =
                make_uint4(f2tf32(kv.x), f2tf32(kv.y), f2tf32(kv.z), f2tf32(kv.w));
            *(uint4*)&Vsm[row * VSS + c] =
                make_uint4(f2tf32(vv.x), f2tf32(vv.y), f2tf32(vv.z), f2tf32(vv.w));
        }
        __syncthreads();

        float s[2][8][4];
        #pragma unroll
        for (int mi = 0; mi < 2; mi++)
            #pragma unroll
            for (int nj = 0; nj < 8; nj++)
                #pragma unroll
                for (int e = 0; e < 4; e++) s[mi][nj][e] = 0.0f;

        #pragma unroll
        for (int ks = 0; ks < 8; ks++) {
            unsigned a[2][4];
            #pragma unroll
            for (int mi = 0; mi < 2; mi++) {
                int m = w * 32 + mi * 16 + gid;
                int k = ks * 8 + tig;
                a[mi][0] = Qs[m * QS + k];
                a[mi][1] = Qs[(m + 8) * QS + k];
                a[mi][2] = Qs[m * QS + k + 4];
                a[mi][3] = Qs[(m + 8) * QS + k + 4];
            }
            #pragma unroll
            for (int nj = 0; nj < 8; nj++) {
                unsigned bf[2];
                int krow = nj * 8 + gid;
                bf[0] = Ksm[krow * KSS + ks * 8 + tig];
                bf[1] = Ksm[krow * KSS + ks * 8 + tig + 4];
                mma_tf32(s[0][nj], a[0], bf);
                mma_tf32(s[1][nj], a[1], bf);
            }
        }

        if (kt >= 2 * qt) {
            int colbase = kt * 64 + 2 * tig;
            int rowbase = qt * 128 + w * 32 + gid;
            #pragma unroll
            for (int mi = 0; mi < 2; mi++)
                #pragma unroll
                for (int nj = 0; nj < 8; nj++)
                    #pragma unroll
                    for (int e = 0; e < 4; e++) {
                        int row = rowbase + mi * 16 + ((e >> 1) << 3);
                        int col = colbase + nj * 8 + (e & 1);
                        if (col > row) s[mi][nj][e] = -1e30f;
                    }
        }

        #pragma unroll
        for (int st = 0; st < 4; st++) {
            const int mi = st >> 1, hf = st & 1;
            float rm = -1e30f;
            #pragma unroll
            for (int nj = 0; nj < 8; nj++) {
                rm = fmaxf(rm, s[mi][nj][hf * 2]);
                rm = fmaxf(rm, s[mi][nj][hf * 2 + 1]);
            }
            rm = fmaxf(rm, __shfl_xor_sync(0xffffffff, rm, 1));
            rm = fmaxf(rm, __shfl_xor_sync(0xffffffff, rm, 2));
            float mnew = fmaxf(mst[st], rm);
            float alpha = ex2f(mst[st] - mnew);
            mst[st] = mnew;
            lst[st] *= alpha;
            #pragma unroll
            for (int nj = 0; nj < 8; nj++) {
                o[mi][nj][hf * 2]     *= alpha;
                o[mi][nj][hf * 2 + 1] *= alpha;
            }
            float psum = 0.0f;
            #pragma unroll
            for (int nj = 0; nj < 8; nj++) {
                float p0 = ex2f(s[mi][nj][hf * 2]     - mnew);
                float p1 = ex2f(s[mi][nj][hf * 2 + 1] - mnew);
                s[mi][nj][hf * 2]     = p0;
                s[mi][nj][hf * 2 + 1] = p1;
                psum += p0 + p1;
            }
            psum += __shfl_xor_sync(0xffffffff, psum, 1);
            psum += __shfl_xor_sync(0xffffffff, psum, 2);
            lst[st] += psum;
        }

        const int src0 = (lane & ~3) | (tig >> 1);
        const int src1 = src0 + 2;
        const bool odd = tig & 1;
        #pragma unroll
        for (int kc = 0; kc < 8; kc++) {
            unsigned pa[2][4];
            #pragma unroll
            for (int mi = 0; mi < 2; mi++) {
                float c0 = s[mi][kc][0], c1 = s[mi][kc][1];
                float c2 = s[mi][kc][2], c3 = s[mi][kc][3];
                float v00 = __shfl_sync(0xffffffff, c0, src0);
                float v01 = __shfl_sync(0xffffffff, c1, src0);
                float v10 = __shfl_sync(0xffffffff, c0, src1);
                float v11 = __shfl_sync(0xffffffff, c1, src1);
                float v20 = __shfl_sync(0xffffffff, c2, src0);
                float v21 = __shfl_sync(0xffffffff, c3, src0);
                float v30 = __shfl_sync(0xffffffff, c2, src1);
                float v31 = __shfl_sync(0xffffffff, c3, src1);
                pa[mi][0] = __float_as_uint(odd ? v01 : v00);
                pa[mi][2] = __float_as_uint(odd ? v11 : v10);
                pa[mi][1] = __float_as_uint(odd ? v21 : v20);
                pa[mi][3] = __float_as_uint(odd ? v31 : v30);
            }
            #pragma unroll
            for (int hj = 0; hj < 8; hj++) {
                unsigned bf[2];
                bf[0] = Vsm[(kc * 8 + tig) * VSS + hj * 8 + gid];
                bf[1] = Vsm[(kc * 8 + tig + 4) * VSS + hj * 8 + gid];
                mma_tf32(o[0][hj], pa[0], bf);
                mma_tf32(o[1][hj], pa[1], bf);
            }
        }
    }

    #pragma unroll
    for (int mi = 0; mi < 2; mi++) {
        float inv0 = 1.0f / lst[2 * mi];
        float inv1 = 1.0f / lst[2 * mi + 1];
        #pragma unroll
        for (int nj = 0; nj < 8; nj++) {
            int row = qt * 128 + w * 32 + mi * 16 + gid;
            int col = nj * 8 + 2 * tig;
            float* op = g_attn + (size_t)(b * TT + row) * CC + h * HD + col;
            *(float2*)op = make_float2(o[mi][nj][0] * inv0, o[mi][nj][1] * inv0);
            *(float2*)(op + (size_t)8 * CC) =
                make_float2(o[mi][nj][2] * inv1, o[mi][nj][3] * inv1);
        }
    }
}

// ---------------------------------------------------------------------------
// Launch
// ---------------------------------------------------------------------------
extern "C" void kernel_launch(void* const* d_in, const int* in_sizes, int n_in,
                              void* d_out, int out_size)
{
    const float* x     = (const float*)d_in[0];   // [B,T,C]
    const float* w_qkv = (const float*)d_in[1];   // [C,3C]
    const float* w_out = (const float*)d_in[2];   // [C,C]
    float* out = (float*)d_out;                   // [B,T,C]

    float* qkv_ptr = nullptr;
    float* attn_ptr = nullptr;
    cudaGetSymbolAddress((void**)&qkv_ptr, g_qkv);
    cudaGetSymbolAddress((void**)&attn_ptr, g_attn);

    cudaFuncSetAttribute(gemm_tf32, cudaFuncAttributeMaxDynamicSharedMemorySize,
                         GEMM_SMEM_BYTES);
    cudaFuncSetAttribute(attn_tc, cudaFuncAttributeMaxDynamicSharedMemorySize,
                         ATT_SMEM_BYTES);

    // 1) QKV projection: [8192,1024] @ [1024,3072]
    {
        dim3 grid(N3 / 128, M_ROWS / 128);
        gemm_tf32<<<grid, 256, GEMM_SMEM_BYTES>>>(x, w_qkv, qkv_ptr, M_ROWS, N3, CC);
    }
    // 2) Flash attention (tensor cores)
    {
        dim3 grid(TT / 128, BB * HH);
        attn_tc<<<grid, 128, ATT_SMEM_BYTES>>>();
    }
    // 3) Output projection: [8192,1024] @ [1024,1024]
    {
        dim3 grid(CC / 128, M_ROWS / 128);
        gemm_tf32<<<grid, 256, GEMM_SMEM_BYTES>>>(attn_ptr, w_out, out, M_ROWS, CC, CC);
    }
}

// round 10
// speedup vs baseline: 1.3600x; 1.3600x over previous
#include <cuda_runtime.h>
#include <math.h>

// Problem constants
#define BB 4
#define TT 2048
#define CC 1024
#define HH 16
#define HD 64
#define M_ROWS (BB * TT)       // 8192
#define N3 (3 * CC)            // 3072

// Scratch (device globals -- allocation API is forbidden).
// All intermediate tensors are stored as tf32 bit patterns (unsigned).
__device__ unsigned g_x_t[(size_t)M_ROWS * CC];        // 33.6 MB  tf32(x)
__device__ unsigned g_wqkv_t[(size_t)CC * N3];         // 12.6 MB  tf32(w_qkv)
__device__ unsigned g_wout_t[(size_t)CC * CC];         //  4.2 MB  tf32(w_out)
__device__ unsigned g_qkv[(size_t)M_ROWS * N3];        // 100.7 MB tf32(qkv)
__device__ unsigned g_attn[(size_t)M_ROWS * CC];       // 33.6 MB  tf32(attn)

// ---------------------------------------------------------------------------
// Helpers
// ---------------------------------------------------------------------------
__device__ __forceinline__ unsigned f2tf32(float x) {
    unsigned r;
    asm("cvt.rna.tf32.f32 %0, %1;" : "=r"(r) : "f"(x));
    return r;
}
__device__ __forceinline__ float ex2f(float x) {
    float r;
    asm("ex2.approx.ftz.f32 %0, %1;" : "=f"(r) : "f"(x));
    return r;
}
__device__ __forceinline__ void mma_tf32(float* d, const unsigned* a, const unsigned* b) {
    asm volatile(
        "mma.sync.aligned.m16n8k8.row.col.f32.tf32.tf32.f32 "
        "{%0,%1,%2,%3}, {%4,%5,%6,%7}, {%8,%9}, {%0,%1,%2,%3};"
        : "+f"(d[0]), "+f"(d[1]), "+f"(d[2]), "+f"(d[3])
        : "r"(a[0]), "r"(a[1]), "r"(a[2]), "r"(a[3]), "r"(b[0]), "r"(b[1]));
}
__device__ __forceinline__ void cpasync16(void* smem, const void* gmem) {
    unsigned saddr = (unsigned)__cvta_generic_to_shared(smem);
    asm volatile("cp.async.cg.shared.global [%0], [%1], 16;" :: "r"(saddr), "l"(gmem));
}
__device__ __forceinline__ void cp_commit() {
    asm volatile("cp.async.commit_group;");
}
template <int N>
__device__ __forceinline__ void cp_wait() {
    asm volatile("cp.async.wait_group %0;" :: "n"(N));
}

extern __shared__ unsigned dynsm_u[];

// ---------------------------------------------------------------------------
// fp32 -> tf32 bit-pattern conversion pre-pass (grid-stride, float4)
// ---------------------------------------------------------------------------
__global__ __launch_bounds__(256)
void cvt_tf32_kernel(const float* __restrict__ src, unsigned* __restrict__ dst,
                     int n4)
{
    for (int i = blockIdx.x * blockDim.x + threadIdx.x; i < n4;
         i += gridDim.x * blockDim.x) {
        float4 v = *(const float4*)(src + (size_t)i * 4);
        uint4 t = make_uint4(f2tf32(v.x), f2tf32(v.y), f2tf32(v.z), f2tf32(v.w));
        *(uint4*)(dst + (size_t)i * 4) = t;
    }
}

// ---------------------------------------------------------------------------
// tf32 tensor GEMM, 3-stage cp.async pipeline, 2 CTAs/SM, NO in-loop cvt.
// A, B are tf32 bit patterns. C stored as tf32 bits (STORE_TF32) or fp32.
// CTA 128x128, BK=32, 256 threads, 8 warps 2(M)x4(N); warp tile 64x32.
// Layouts identical to R6 (proven conflict-free): As[m][k] stride 36,
// Bs[k][n] stride 136.
// ---------------------------------------------------------------------------
#define GAS 36
#define GBS 136
#define GSTAGES 3
#define GSTAGE_W (128 * GAS + 32 * GBS)            // 8960 words
#define GEMM_SMEM_BYTES (GSTAGES * GSTAGE_W * 4)   // 107520

template <bool STORE_TF32>
__global__ __launch_bounds__(256, 2)
void gemm_tf32(const unsigned* __restrict__ A, const unsigned* __restrict__ B,
               void* __restrict__ Cv, int M, int N, int K)
{
    const int tid  = threadIdx.x;
    const int lane = tid & 31;
    const int wid  = tid >> 5;
    const int gid  = lane >> 2;
    const int tig  = lane & 3;
    const int wm   = wid >> 2;     // 0..1
    const int wn   = wid & 3;      // 0..3
    const int bM   = blockIdx.y * 128;
    const int bN   = blockIdx.x * 128;

    auto load_stage = [&](int s, int kb) {
        unsigned* As = dynsm_u + s * GSTAGE_W;
        unsigned* Bs = As + 128 * GAS;
        #pragma unroll
        for (int r = 0; r < 4; r++) {
            int idx = tid + r * 256;
            int row = idx >> 3;
            int c   = (idx & 7) * 4;
            cpasync16(&As[row * GAS + c], A + (size_t)(bM + row) * K + kb + c);
        }
        #pragma unroll
        for (int r = 0; r < 4; r++) {
            int idx = tid + r * 256;
            int row = idx >> 5;
            int c   = (idx & 31) * 4;
            cpasync16(&Bs[row * GBS + c], B + (size_t)(kb + row) * N + bN + c);
        }
    };

    const int ntile = K >> 5;
    #pragma unroll
    for (int s = 0; s < GSTAGES - 1; s++) {
        if (s < ntile) load_stage(s, s * 32);
        cp_commit();
    }

    float acc[4][4][4];
    #pragma unroll
    for (int mi = 0; mi < 4; mi++)
        #pragma unroll
        for (int nj = 0; nj < 4; nj++)
            #pragma unroll
            for (int e = 0; e < 4; e++) acc[mi][nj][e] = 0.0f;

    for (int i = 0; i < ntile; i++) {
        cp_wait<GSTAGES - 2>();
        __syncthreads();

        int nt = i + GSTAGES - 1;
        if (nt < ntile) load_stage(nt % GSTAGES, nt * 32);
        cp_commit();

        const unsigned* As = dynsm_u + (i % GSTAGES) * GSTAGE_W;
        const unsigned* Bs = As + 128 * GAS;

        #pragma unroll
        for (int ks = 0; ks < 4; ks++) {
            unsigned af[4][4], bf[4][2];
            #pragma unroll
            for (int mi = 0; mi < 4; mi++) {
                int m = wm * 64 + mi * 16 + gid;
                int k = ks * 8 + tig;
                af[mi][0] = As[m * GAS + k];
                af[mi][1] = As[(m + 8) * GAS + k];
                af[mi][2] = As[m * GAS + k + 4];
                af[mi][3] = As[(m + 8) * GAS + k + 4];
            }
            #pragma unroll
            for (int nj = 0; nj < 4; nj++) {
                int n = wn * 32 + nj * 8 + gid;
                int k = ks * 8 + tig;
                bf[nj][0] = Bs[k * GBS + n];
                bf[nj][1] = Bs[(k + 4) * GBS + n];
            }
            #pragma unroll
            for (int mi = 0; mi < 4; mi++)
                #pragma unroll
                for (int nj = 0; nj < 4; nj++)
                    mma_tf32(acc[mi][nj], af[mi], bf[nj]);
        }
    }

    // Epilogue
    #pragma unroll
    for (int mi = 0; mi < 4; mi++) {
        #pragma unroll
        for (int nj = 0; nj < 4; nj++) {
            int row = bM + wm * 64 + mi * 16 + gid;
            int col = bN + wn * 32 + nj * 8 + 2 * tig;
            if (STORE_TF32) {
                unsigned* C = (unsigned*)Cv;
                *(uint2*)(C + (size_t)row * N + col) =
                    make_uint2(f2tf32(acc[mi][nj][0]), f2tf32(acc[mi][nj][1]));
                *(uint2*)(C + (size_t)(row + 8) * N + col) =
                    make_uint2(f2tf32(acc[mi][nj][2]), f2tf32(acc[mi][nj][3]));
            } else {
                float* C = (float*)Cv;
                *(float2*)(C + (size_t)row * N + col) =
                    make_float2(acc[mi][nj][0], acc[mi][nj][1]);
                *(float2*)(C + (size_t)(row + 8) * N + col) =
                    make_float2(acc[mi][nj][2], acc[mi][nj][3]);
            }
        }
    }
}

// ---------------------------------------------------------------------------
// Tensor-core flash attention (causal, tf32 mma, fp32 accum).
// Inputs already tf32 bits -> staging is pure cp.async. Softmax scale applied
// to S in fp32 post-mma. Output written as tf32 bits for the out-proj GEMM.
// CTA: 128 query rows, 4 warps x 32 rows. 64-key tiles. R6 layouts.
// ---------------------------------------------------------------------------
#define QS 68
#define KSS 68
#define VSS 72
#define ATT_SMEM_WORDS (128 * QS + 64 * KSS + 64 * VSS)   // 17664
#define ATT_SMEM_BYTES (ATT_SMEM_WORDS * 4)               // 70656
#define SM_SCALE (0.125f * 1.44269504f)   // 1/sqrt(64) * log2(e)

__global__ __launch_bounds__(128)
void attn_tc()
{
    unsigned* Qs  = dynsm_u;
    unsigned* Ksm = dynsm_u + 128 * QS;
    unsigned* Vsm = Ksm + 64 * KSS;

    const int tid  = threadIdx.x;
    const int lane = tid & 31;
    const int w    = tid >> 5;
    const int gid  = lane >> 2;
    const int tig  = lane & 3;
    const int qt   = blockIdx.x;
    const int bh   = blockIdx.y;
    const int b    = bh >> 4;
    const int h    = bh & 15;

    const unsigned* base = g_qkv + (size_t)b * TT * N3;

    // Stage Q tile (128 x 64) -- raw tf32 copy
    #pragma unroll
    for (int r = 0; r < 16; r++) {
        int idx = tid + r * 128;
        int row = idx >> 4;
        int c   = (idx & 15) * 4;
        cpasync16(&Qs[row * QS + c],
                  base + (size_t)(qt * 128 + row) * N3 + h * HD + c);
    }
    cp_commit();

    float o[2][8][4];
    #pragma unroll
    for (int mi = 0; mi < 2; mi++)
        #pragma unroll
        for (int nj = 0; nj < 8; nj++)
            #pragma unroll
            for (int e = 0; e < 4; e++) o[mi][nj][e] = 0.0f;
    float mst[4] = {-1e30f, -1e30f, -1e30f, -1e30f};
    float lst[4] = {0.f, 0.f, 0.f, 0.f};

    const int ntiles = 2 * qt + 2;

    for (int kt = 0; kt < ntiles; kt++) {
        __syncthreads();   // all warps done reading previous K/V
        const unsigned* kb_ = base + (size_t)(kt * 64) * N3 + CC + h * HD;
        const unsigned* vb_ = base + (size_t)(kt * 64) * N3 + 2 * CC + h * HD;
        #pragma unroll
        for (int r = 0; r < 8; r++) {
            int idx = tid + r * 128;
            int row = idx >> 4;
            int c   = (idx & 15) * 4;
            cpasync16(&Ksm[row * KSS + c], kb_ + (size_t)row * N3 + c);
            cpasync16(&Vsm[row * VSS + c], vb_ + (size_t)row * N3 + c);
        }
        cp_commit();
        cp_wait<0>();
        __syncthreads();

        // --- S = Q @ K^T ---
        float s[2][8][4];
        #pragma unroll
        for (int mi = 0; mi < 2; mi++)
            #pragma unroll
            for (int nj = 0; nj < 8; nj++)
                #pragma unroll
                for (int e = 0; e < 4; e++) s[mi][nj][e] = 0.0f;

        #pragma unroll
        for (int ks = 0; ks < 8; ks++) {
            unsigned a[2][4];
            #pragma unroll
            for (int mi = 0; mi < 2; mi++) {
                int m = w * 32 + mi * 16 + gid;
                int k = ks * 8 + tig;
                a[mi][0] = Qs[m * QS + k];
                a[mi][1] = Qs[(m + 8) * QS + k];
                a[mi][2] = Qs[m * QS + k + 4];
                a[mi][3] = Qs[(m + 8) * QS + k + 4];
            }
            #pragma unroll
            for (int nj = 0; nj < 8; nj++) {
                unsigned bf[2];
                int krow = nj * 8 + gid;
                bf[0] = Ksm[krow * KSS + ks * 8 + tig];
                bf[1] = Ksm[krow * KSS + ks * 8 + tig + 4];
                mma_tf32(s[0][nj], a[0], bf);
                mma_tf32(s[1][nj], a[1], bf);
            }
        }

        // scale into log2 domain
        #pragma unroll
        for (int mi = 0; mi < 2; mi++)
            #pragma unroll
            for (int nj = 0; nj < 8; nj++)
                #pragma unroll
                for (int e = 0; e < 4; e++) s[mi][nj][e] *= SM_SCALE;

        // --- causal mask (only the two diagonal tiles) ---
        if (kt >= 2 * qt) {
            int colbase = kt * 64 + 2 * tig;
            int rowbase = qt * 128 + w * 32 + gid;
            #pragma unroll
            for (int mi = 0; mi < 2; mi++)
                #pragma unroll
                for (int nj = 0; nj < 8; nj++)
                    #pragma unroll
                    for (int e = 0; e < 4; e++) {
                        int row = rowbase + mi * 16 + ((e >> 1) << 3);
                        int col = colbase + nj * 8 + (e & 1);
                        if (col > row) s[mi][nj][e] = -1e30f;
                    }
        }

        // --- online softmax update (base-2) ---
        #pragma unroll
        for (int st = 0; st < 4; st++) {
            const int mi = st >> 1, hf = st & 1;
            float rm = -1e30f;
            #pragma unroll
            for (int nj = 0; nj < 8; nj++) {
                rm = fmaxf(rm, s[mi][nj][hf * 2]);
                rm = fmaxf(rm, s[mi][nj][hf * 2 + 1]);
            }
            rm = fmaxf(rm, __shfl_xor_sync(0xffffffff, rm, 1));
            rm = fmaxf(rm, __shfl_xor_sync(0xffffffff, rm, 2));
            float mnew = fmaxf(mst[st], rm);
            float alpha = ex2f(mst[st] - mnew);
            mst[st] = mnew;
            lst[st] *= alpha;
            #pragma unroll
            for (int nj = 0; nj < 8; nj++) {
                o[mi][nj][hf * 2]     *= alpha;
                o[mi][nj][hf * 2 + 1] *= alpha;
            }
            float psum = 0.0f;
            #pragma unroll
            for (int nj = 0; nj < 8; nj++) {
                float p0 = ex2f(s[mi][nj][hf * 2]     - mnew);
                float p1 = ex2f(s[mi][nj][hf * 2 + 1] - mnew);
                s[mi][nj][hf * 2]     = p0;
                s[mi][nj][hf * 2 + 1] = p1;
                psum += p0 + p1;
            }
            psum += __shfl_xor_sync(0xffffffff, psum, 1);
            psum += __shfl_xor_sync(0xffffffff, psum, 2);
            lst[st] += psum;
        }

        // --- O += P @ V ---
        const int src0 = (lane & ~3) | (tig >> 1);
        const int src1 = src0 + 2;
        const bool odd = tig & 1;
        #pragma unroll
        for (int kc = 0; kc < 8; kc++) {
            unsigned pa[2][4];
            #pragma unroll
            for (int mi = 0; mi < 2; mi++) {
                float c0 = s[mi][kc][0], c1 = s[mi][kc][1];
                float c2 = s[mi][kc][2], c3 = s[mi][kc][3];
                float v00 = __shfl_sync(0xffffffff, c0, src0);
                float v01 = __shfl_sync(0xffffffff, c1, src0);
                float v10 = __shfl_sync(0xffffffff, c0, src1);
                float v11 = __shfl_sync(0xffffffff, c1, src1);
                float v20 = __shfl_sync(0xffffffff, c2, src0);
                float v21 = __shfl_sync(0xffffffff, c3, src0);
                float v30 = __shfl_sync(0xffffffff, c2, src1);
                float v31 = __shfl_sync(0xffffffff, c3, src1);
                pa[mi][0] = __float_as_uint(odd ? v01 : v00);
                pa[mi][2] = __float_as_uint(odd ? v11 : v10);
                pa[mi][1] = __float_as_uint(odd ? v21 : v20);
                pa[mi][3] = __float_as_uint(odd ? v31 : v30);
            }
            #pragma unroll
            for (int hj = 0; hj < 8; hj++) {
                unsigned bf[2];
                bf[0] = Vsm[(kc * 8 + tig) * VSS + hj * 8 + gid];
                bf[1] = Vsm[(kc * 8 + tig + 4) * VSS + hj * 8 + gid];
                mma_tf32(o[0][hj], pa[0], bf);
                mma_tf32(o[1][hj], pa[1], bf);
            }
        }
    }

    // --- normalize + write tf32 bits in [B,T,C] layout ---
    #pragma unroll
    for (int mi = 0; mi < 2; mi++) {
        float inv0 = 1.0f / lst[2 * mi];
        float inv1 = 1.0f / lst[2 * mi + 1];
        #pragma unroll
        for (int nj = 0; nj < 8; nj++) {
            int row = qt * 128 + w * 32 + mi * 16 + gid;
            int col = nj * 8 + 2 * tig;
            unsigned* op = g_attn + (size_t)(b * TT + row) * CC + h * HD + col;
            *(uint2*)op = make_uint2(f2tf32(o[mi][nj][0] * inv0),
                                     f2tf32(o[mi][nj][1] * inv0));
            *(uint2*)(op + (size_t)8 * CC) =
                make_uint2(f2tf32(o[mi][nj][2] * inv1),
                           f2tf32(o[mi][nj][3] * inv1));
        }
    }
}

// ---------------------------------------------------------------------------
// Launch
// ---------------------------------------------------------------------------
extern "C" void kernel_launch(void* const* d_in, const int* in_sizes, int n_in,
                              void* d_out, int out_size)
{
    const float* x     = (const float*)d_in[0];   // [B,T,C]
    const float* w_qkv = (const float*)d_in[1];   // [C,3C]
    const float* w_out = (const float*)d_in[2];   // [C,C]
    float* out = (float*)d_out;                   // [B,T,C]

    unsigned *xt, *wqkvt, *woutt, *qkv_ptr, *attn_ptr;
    cudaGetSymbolAddress((void**)&xt, g_x_t);
    cudaGetSymbolAddress((void**)&wqkvt, g_wqkv_t);
    cudaGetSymbolAddress((void**)&woutt, g_wout_t);
    cudaGetSymbolAddress((void**)&qkv_ptr, g_qkv);
    cudaGetSymbolAddress((void**)&attn_ptr, g_attn);

    cudaFuncSetAttribute(gemm_tf32<true>,
                         cudaFuncAttributeMaxDynamicSharedMemorySize, GEMM_SMEM_BYTES);
    cudaFuncSetAttribute(gemm_tf32<false>,
                         cudaFuncAttributeMaxDynamicSharedMemorySize, GEMM_SMEM_BYTES);
    cudaFuncSetAttribute(attn_tc,
                         cudaFuncAttributeMaxDynamicSharedMemorySize, ATT_SMEM_BYTES);

    // 0) tf32 conversion pre-pass
    cvt_tf32_kernel<<<1024, 256>>>(x, xt, (M_ROWS * CC) / 4);
    cvt_tf32_kernel<<<512, 256>>>(w_qkv, wqkvt, (CC * N3) / 4);
    cvt_tf32_kernel<<<256, 256>>>(w_out, woutt, (CC * CC) / 4);

    // 1) QKV projection: [8192,1024] @ [1024,3072] -> tf32 bits
    {
        dim3 grid(N3 / 128, M_ROWS / 128);
        gemm_tf32<true><<<grid, 256, GEMM_SMEM_BYTES>>>(xt, wqkvt, qkv_ptr,
                                                        M_ROWS, N3, CC);
    }
    // 2) Flash attention (tensor cores) -> tf32 bits
    {
        dim3 grid(TT / 128, BB * HH);
        attn_tc<<<grid, 128, ATT_SMEM_BYTES>>>();
    }
    // 3) Output projection: [8192,1024] @ [1024,1024] -> fp32 out
    {
        dim3 grid(CC / 128, M_ROWS / 128);
        gemm_tf32<false><<<grid, 256, GEMM_SMEM_BYTES>>>(attn_ptr, woutt, out,
                                                         M_ROWS, CC, CC);
    }
}

// round 12
// speedup vs baseline: 1.4176x; 1.0423x over previous
#include <cuda_runtime.h>
#include <math.h>

// Problem constants
#define BB 4
#define TT 2048
#define CC 1024
#define HH 16
#define HD 64
#define M_ROWS (BB * TT)       // 8192
#define N3 (3 * CC)            // 3072

// Scratch (device globals -- allocation API is forbidden).
// All intermediate tensors are stored as tf32 bit patterns (unsigned).
__device__ unsigned g_x_t[(size_t)M_ROWS * CC];        // 33.6 MB  tf32(x)
__device__ unsigned g_wqkv_t[(size_t)CC * N3];         // 12.6 MB  tf32(w_qkv)
__device__ unsigned g_wout_t[(size_t)CC * CC];         //  4.2 MB  tf32(w_out)
__device__ unsigned g_qkv[(size_t)M_ROWS * N3];        // 100.7 MB tf32(qkv)
__device__ unsigned g_attn[(size_t)M_ROWS * CC];       // 33.6 MB  tf32(attn)

// ---------------------------------------------------------------------------
// Helpers
// ---------------------------------------------------------------------------
__device__ __forceinline__ unsigned f2tf32(float x) {
    unsigned r;
    asm("cvt.rna.tf32.f32 %0, %1;" : "=r"(r) : "f"(x));
    return r;
}
__device__ __forceinline__ float ex2f(float x) {
    float r;
    asm("ex2.approx.ftz.f32 %0, %1;" : "=f"(r) : "f"(x));
    return r;
}
__device__ __forceinline__ void mma_tf32(float* d, const unsigned* a, const unsigned* b) {
    asm volatile(
        "mma.sync.aligned.m16n8k8.row.col.f32.tf32.tf32.f32 "
        "{%0,%1,%2,%3}, {%4,%5,%6,%7}, {%8,%9}, {%0,%1,%2,%3};"
        : "+f"(d[0]), "+f"(d[1]), "+f"(d[2]), "+f"(d[3])
        : "r"(a[0]), "r"(a[1]), "r"(a[2]), "r"(a[3]), "r"(b[0]), "r"(b[1]));
}
__device__ __forceinline__ void cpasync16(void* smem, const void* gmem) {
    unsigned saddr = (unsigned)__cvta_generic_to_shared(smem);
    asm volatile("cp.async.cg.shared.global [%0], [%1], 16;" :: "r"(saddr), "l"(gmem));
}
__device__ __forceinline__ void cp_commit() {
    asm volatile("cp.async.commit_group;");
}
template <int N>
__device__ __forceinline__ void cp_wait() {
    asm volatile("cp.async.wait_group %0;" :: "n"(N));
}

extern __shared__ unsigned dynsm_u[];

// ---------------------------------------------------------------------------
// fp32 -> tf32 bit-pattern conversion pre-pass (grid-stride, float4)
// ---------------------------------------------------------------------------
__global__ __launch_bounds__(256)
void cvt_tf32_kernel(const float* __restrict__ src, unsigned* __restrict__ dst,
                     int n4)
{
    for (int i = blockIdx.x * blockDim.x + threadIdx.x; i < n4;
         i += gridDim.x * blockDim.x) {
        float4 v = *(const float4*)(src + (size_t)i * 4);
        uint4 t = make_uint4(f2tf32(v.x), f2tf32(v.y), f2tf32(v.z), f2tf32(v.w));
        *(uint4*)(dst + (size_t)i * 4) = t;
    }
}

// ---------------------------------------------------------------------------
// tf32 tensor GEMM, 3-stage cp.async pipeline, 2 CTAs/SM, NO in-loop cvt.
// (unchanged from R10: 317us, tensor 54%)
// ---------------------------------------------------------------------------
#define GAS 36
#define GBS 136
#define GSTAGES 3
#define GSTAGE_W (128 * GAS + 32 * GBS)            // 8960 words
#define GEMM_SMEM_BYTES (GSTAGES * GSTAGE_W * 4)   // 107520

template <bool STORE_TF32>
__global__ __launch_bounds__(256, 2)
void gemm_tf32(const unsigned* __restrict__ A, const unsigned* __restrict__ B,
               void* __restrict__ Cv, int M, int N, int K)
{
    const int tid  = threadIdx.x;
    const int lane = tid & 31;
    const int wid  = tid >> 5;
    const int gid  = lane >> 2;
    const int tig  = lane & 3;
    const int wm   = wid >> 2;     // 0..1
    const int wn   = wid & 3;      // 0..3
    const int bM   = blockIdx.y * 128;
    const int bN   = blockIdx.x * 128;

    auto load_stage = [&](int s, int kb) {
        unsigned* As = dynsm_u + s * GSTAGE_W;
        unsigned* Bs = As + 128 * GAS;
        #pragma unroll
        for (int r = 0; r < 4; r++) {
            int idx = tid + r * 256;
            int row = idx >> 3;
            int c   = (idx & 7) * 4;
            cpasync16(&As[row * GAS + c], A + (size_t)(bM + row) * K + kb + c);
        }
        #pragma unroll
        for (int r = 0; r < 4; r++) {
            int idx = tid + r * 256;
            int row = idx >> 5;
            int c   = (idx & 31) * 4;
            cpasync16(&Bs[row * GBS + c], B + (size_t)(kb + row) * N + bN + c);
        }
    };

    const int ntile = K >> 5;
    #pragma unroll
    for (int s = 0; s < GSTAGES - 1; s++) {
        if (s < ntile) load_stage(s, s * 32);
        cp_commit();
    }

    float acc[4][4][4];
    #pragma unroll
    for (int mi = 0; mi < 4; mi++)
        #pragma unroll
        for (int nj = 0; nj < 4; nj++)
            #pragma unroll
            for (int e = 0; e < 4; e++) acc[mi][nj][e] = 0.0f;

    for (int i = 0; i < ntile; i++) {
        cp_wait<GSTAGES - 2>();
        __syncthreads();

        int nt = i + GSTAGES - 1;
        if (nt < ntile) load_stage(nt % GSTAGES, nt * 32);
        cp_commit();

        const unsigned* As = dynsm_u + (i % GSTAGES) * GSTAGE_W;
        const unsigned* Bs = As + 128 * GAS;

        #pragma unroll
        for (int ks = 0; ks < 4; ks++) {
            unsigned af[4][4], bf[4][2];
            #pragma unroll
            for (int mi = 0; mi < 4; mi++) {
                int m = wm * 64 + mi * 16 + gid;
                int k = ks * 8 + tig;
                af[mi][0] = As[m * GAS + k];
                af[mi][1] = As[(m + 8) * GAS + k];
                af[mi][2] = As[m * GAS + k + 4];
                af[mi][3] = As[(m + 8) * GAS + k + 4];
            }
            #pragma unroll
            for (int nj = 0; nj < 4; nj++) {
                int n = wn * 32 + nj * 8 + gid;
                int k = ks * 8 + tig;
                bf[nj][0] = Bs[k * GBS + n];
                bf[nj][1] = Bs[(k + 4) * GBS + n];
            }
            #pragma unroll
            for (int mi = 0; mi < 4; mi++)
                #pragma unroll
                for (int nj = 0; nj < 4; nj++)
                    mma_tf32(acc[mi][nj], af[mi], bf[nj]);
        }
    }

    // Epilogue
    #pragma unroll
    for (int mi = 0; mi < 4; mi++) {
        #pragma unroll
        for (int nj = 0; nj < 4; nj++) {
            int row = bM + wm * 64 + mi * 16 + gid;
            int col = bN + wn * 32 + nj * 8 + 2 * tig;
            if (STORE_TF32) {
                unsigned* C = (unsigned*)Cv;
                *(uint2*)(C + (size_t)row * N + col) =
                    make_uint2(f2tf32(acc[mi][nj][0]), f2tf32(acc[mi][nj][1]));
                *(uint2*)(C + (size_t)(row + 8) * N + col) =
                    make_uint2(f2tf32(acc[mi][nj][2]), f2tf32(acc[mi][nj][3]));
            } else {
                float* C = (float*)Cv;
                *(float2*)(C + (size_t)row * N + col) =
                    make_float2(acc[mi][nj][0], acc[mi][nj][1]);
                *(float2*)(C + (size_t)(row + 8) * N + col) =
                    make_float2(acc[mi][nj][2], acc[mi][nj][3]);
            }
        }
    }
}

// ---------------------------------------------------------------------------
// Tensor-core flash attention (causal, tf32 mma, fp32 accum).
// DOUBLE-BUFFERED K/V: cp_wait<0> -> sync -> issue next tile -> compute.
// Compute of tile kt overlaps loads of tile kt+1. Reverse-qt launch order.
// CTA: 128 query rows, 4 warps x 32 rows. 64-key tiles. R6 layouts.
// ---------------------------------------------------------------------------
#define QS 68
#define KSS 68
#define VSS 72
#define ATT_Q_W   (128 * QS)            // 8704 words
#define ATT_KV_W  (64 * KSS + 64 * VSS) // 8960 words per stage
#define ATT_SMEM_BYTES ((ATT_Q_W + 2 * ATT_KV_W) * 4)   // 106496
#define SM_SCALE (0.125f * 1.44269504f)   // 1/sqrt(64) * log2(e)

__global__ __launch_bounds__(128)
void attn_tc()
{
    unsigned* Qs = dynsm_u;
    unsigned* Kb[2];
    unsigned* Vb[2];
    Kb[0] = dynsm_u + ATT_Q_W;
    Vb[0] = Kb[0] + 64 * KSS;
    Kb[1] = dynsm_u + ATT_Q_W + ATT_KV_W;
    Vb[1] = Kb[1] + 64 * KSS;

    const int tid  = threadIdx.x;
    const int lane = tid & 31;
    const int w    = tid >> 5;
    const int gid  = lane >> 2;
    const int tig  = lane & 3;
    const int qt   = (int)(gridDim.x - 1 - blockIdx.x);   // heavy tiles first
    const int bh   = blockIdx.y;
    const int b    = bh >> 4;
    const int h    = bh & 15;

    const unsigned* base = g_qkv + (size_t)b * TT * N3;

    // Stage Q tile (128 x 64) -- raw tf32 copy (group: Q)
    #pragma unroll
    for (int r = 0; r < 16; r++) {
        int idx = tid + r * 128;
        int row = idx >> 4;
        int c   = (idx & 15) * 4;
        cpasync16(&Qs[row * QS + c],
                  base + (size_t)(qt * 128 + row) * N3 + h * HD + c);
    }
    cp_commit();

    auto load_kv = [&](int s, int kt) {
        const unsigned* kb_ = base + (size_t)(kt * 64) * N3 + CC + h * HD;
        const unsigned* vb_ = base + (size_t)(kt * 64) * N3 + 2 * CC + h * HD;
        #pragma unroll
        for (int r = 0; r < 8; r++) {
            int idx = tid + r * 128;
            int row = idx >> 4;
            int c   = (idx & 15) * 4;
            cpasync16(&Kb[s][row * KSS + c], kb_ + (size_t)row * N3 + c);
            cpasync16(&Vb[s][row * VSS + c], vb_ + (size_t)row * N3 + c);
        }
        cp_commit();
    };

    float o[2][8][4];
    #pragma unroll
    for (int mi = 0; mi < 2; mi++)
        #pragma unroll
        for (int nj = 0; nj < 8; nj++)
            #pragma unroll
            for (int e = 0; e < 4; e++) o[mi][nj][e] = 0.0f;
    float mst[4] = {-1e30f, -1e30f, -1e30f, -1e30f};
    float lst[4] = {0.f, 0.f, 0.f, 0.f};

    const int ntiles = 2 * qt + 2;

    load_kv(0, 0);

    for (int kt = 0; kt < ntiles; kt++) {
        cp_wait<0>();        // KV(kt) (and Q on first iter) complete
        __syncthreads();     // all warps past previous compute; buffer swap safe

        if (kt + 1 < ntiles) load_kv((kt + 1) & 1, kt + 1);   // overlaps compute

        const unsigned* Ksm = Kb[kt & 1];
        const unsigned* Vsm = Vb[kt & 1];

        // --- S = Q @ K^T ---
        float s[2][8][4];
        #pragma unroll
        for (int mi = 0; mi < 2; mi++)
            #pragma unroll
            for (int nj = 0; nj < 8; nj++)
                #pragma unroll
                for (int e = 0; e < 4; e++) s[mi][nj][e] = 0.0f;

        #pragma unroll
        for (int ks = 0; ks < 8; ks++) {
            unsigned a[2][4];
            #pragma unroll
            for (int mi = 0; mi < 2; mi++) {
                int m = w * 32 + mi * 16 + gid;
                int k = ks * 8 + tig;
                a[mi][0] = Qs[m * QS + k];
                a[mi][1] = Qs[(m + 8) * QS + k];
                a[mi][2] = Qs[m * QS + k + 4];
                a[mi][3] = Qs[(m + 8) * QS + k + 4];
            }
            #pragma unroll
            for (int nj = 0; nj < 8; nj++) {
                unsigned bf[2];
                int krow = nj * 8 + gid;
                bf[0] = Ksm[krow * KSS + ks * 8 + tig];
                bf[1] = Ksm[krow * KSS + ks * 8 + tig + 4];
                mma_tf32(s[0][nj], a[0], bf);
                mma_tf32(s[1][nj], a[1], bf);
            }
        }

        // scale into log2 domain
        #pragma unroll
        for (int mi = 0; mi < 2; mi++)
            #pragma unroll
            for (int nj = 0; nj < 8; nj++)
                #pragma unroll
                for (int e = 0; e < 4; e++) s[mi][nj][e] *= SM_SCALE;

        // --- causal mask (only the two diagonal tiles) ---
        if (kt >= 2 * qt) {
            int colbase = kt * 64 + 2 * tig;
            int rowbase = qt * 128 + w * 32 + gid;
            #pragma unroll
            for (int mi = 0; mi < 2; mi++)
                #pragma unroll
                for (int nj = 0; nj < 8; nj++)
                    #pragma unroll
                    for (int e = 0; e < 4; e++) {
                        int row = rowbase + mi * 16 + ((e >> 1) << 3);
                        int col = colbase + nj * 8 + (e & 1);
                        if (col > row) s[mi][nj][e] = -1e30f;
                    }
        }

        // --- online softmax update (base-2) ---
        #pragma unroll
        for (int st = 0; st < 4; st++) {
            const int mi = st >> 1, hf = st & 1;
            float rm = -1e30f;
            #pragma unroll
            for (int nj = 0; nj < 8; nj++) {
                rm = fmaxf(rm, s[mi][nj][hf * 2]);
                rm = fmaxf(rm, s[mi][nj][hf * 2 + 1]);
            }
            rm = fmaxf(rm, __shfl_xor_sync(0xffffffff, rm, 1));
            rm = fmaxf(rm, __shfl_xor_sync(0xffffffff, rm, 2));
            float mnew = fmaxf(mst[st], rm);
            float alpha = ex2f(mst[st] - mnew);
            mst[st] = mnew;
            lst[st] *= alpha;
            #pragma unroll
            for (int nj = 0; nj < 8; nj++) {
                o[mi][nj][hf * 2]     *= alpha;
                o[mi][nj][hf * 2 + 1] *= alpha;
            }
            float psum = 0.0f;
            #pragma unroll
            for (int nj = 0; nj < 8; nj++) {
                float p0 = ex2f(s[mi][nj][hf * 2]     - mnew);
                float p1 = ex2f(s[mi][nj][hf * 2 + 1] - mnew);
                s[mi][nj][hf * 2]     = p0;
                s[mi][nj][hf * 2 + 1] = p1;
                psum += p0 + p1;
            }
            psum += __shfl_xor_sync(0xffffffff, psum, 1);
            psum += __shfl_xor_sync(0xffffffff, psum, 2);
            lst[st] += psum;
        }

        // --- O += P @ V ---
        const int src0 = (lane & ~3) | (tig >> 1);
        const int src1 = src0 + 2;
        const bool odd = tig & 1;
        #pragma unroll
        for (int kc = 0; kc < 8; kc++) {
            unsigned pa[2][4];
            #pragma unroll
            for (int mi = 0; mi < 2; mi++) {
                float c0 = s[mi][kc][0], c1 = s[mi][kc][1];
                float c2 = s[mi][kc][2], c3 = s[mi][kc][3];
                float v00 = __shfl_sync(0xffffffff, c0, src0);
                float v01 = __shfl_sync(0xffffffff, c1, src0);
                float v10 = __shfl_sync(0xffffffff, c0, src1);
                float v11 = __shfl_sync(0xffffffff, c1, src1);
                float v20 = __shfl_sync(0xffffffff, c2, src0);
                float v21 = __shfl_sync(0xffffffff, c3, src0);
                float v30 = __shfl_sync(0xffffffff, c2, src1);
                float v31 = __shfl_sync(0xffffffff, c3, src1);
                pa[mi][0] = __float_as_uint(odd ? v01 : v00);
                pa[mi][2] = __float_as_uint(odd ? v11 : v10);
                pa[mi][1] = __float_as_uint(odd ? v21 : v20);
                pa[mi][3] = __float_as_uint(odd ? v31 : v30);
            }
            #pragma unroll
            for (int hj = 0; hj < 8; hj++) {
                unsigned bf[2];
                bf[0] = Vsm[(kc * 8 + tig) * VSS + hj * 8 + gid];
                bf[1] = Vsm[(kc * 8 + tig + 4) * VSS + hj * 8 + gid];
                mma_tf32(o[0][hj], pa[0], bf);
                mma_tf32(o[1][hj], pa[1], bf);
            }
        }
    }

    // --- normalize + write tf32 bits in [B,T,C] layout ---
    #pragma unroll
    for (int mi = 0; mi < 2; mi++) {
        float inv0 = 1.0f / lst[2 * mi];
        float inv1 = 1.0f / lst[2 * mi + 1];
        #pragma unroll
        for (int nj = 0; nj < 8; nj++) {
            int row = qt * 128 + w * 32 + mi * 16 + gid;
            int col = nj * 8 + 2 * tig;
            unsigned* op = g_attn + (size_t)(b * TT + row) * CC + h * HD + col;
            *(uint2*)op = make_uint2(f2tf32(o[mi][nj][0] * inv0),
                                     f2tf32(o[mi][nj][1] * inv0));
            *(uint2*)(op + (size_t)8 * CC) =
                make_uint2(f2tf32(o[mi][nj][2] * inv1),
                           f2tf32(o[mi][nj][3] * inv1));
        }
    }
}

// ---------------------------------------------------------------------------
// Launch
// ---------------------------------------------------------------------------
extern "C" void kernel_launch(void* const* d_in, const int* in_sizes, int n_in,
                              void* d_out, int out_size)
{
    const float* x     = (const float*)d_in[0];   // [B,T,C]
    const float* w_qkv = (const float*)d_in[1];   // [C,3C]
    const float* w_out = (const float*)d_in[2];   // [C,C]
    float* out = (float*)d_out;                   // [B,T,C]

    unsigned *xt, *wqkvt, *woutt, *qkv_ptr, *attn_ptr;
    cudaGetSymbolAddress((void**)&xt, g_x_t);
    cudaGetSymbolAddress((void**)&wqkvt, g_wqkv_t);
    cudaGetSymbolAddress((void**)&woutt, g_wout_t);
    cudaGetSymbolAddress((void**)&qkv_ptr, g_qkv);
    cudaGetSymbolAddress((void**)&attn_ptr, g_attn);

    cudaFuncSetAttribute(gemm_tf32<true>,
                         cudaFuncAttributeMaxDynamicSharedMemorySize, GEMM_SMEM_BYTES);
    cudaFuncSetAttribute(gemm_tf32<false>,
                         cudaFuncAttributeMaxDynamicSharedMemorySize, GEMM_SMEM_BYTES);
    cudaFuncSetAttribute(attn_tc,
                         cudaFuncAttributeMaxDynamicSharedMemorySize, ATT_SMEM_BYTES);

    // 0) tf32 conversion pre-pass
    cvt_tf32_kernel<<<1024, 256>>>(x, xt, (M_ROWS * CC) / 4);
    cvt_tf32_kernel<<<512, 256>>>(w_qkv, wqkvt, (CC * N3) / 4);
    cvt_tf32_kernel<<<256, 256>>>(w_out, woutt, (CC * CC) / 4);

    // 1) QKV projection: [8192,1024] @ [1024,3072] -> tf32 bits
    {
        dim3 grid(N3 / 128, M_ROWS / 128);
        gemm_tf32<true><<<grid, 256, GEMM_SMEM_BYTES>>>(xt, wqkvt, qkv_ptr,
                                                        M_ROWS, N3, CC);
    }
    // 2) Flash attention (tensor cores, double-buffered K/V)
    {
        dim3 grid(TT / 128, BB * HH);
        attn_tc<<<grid, 128, ATT_SMEM_BYTES>>>();
    }
    // 3) Output projection: [8192,1024] @ [1024,1024] -> fp32 out
    {
        dim3 grid(CC / 128, M_ROWS / 128);
        gemm_tf32<false><<<grid, 256, GEMM_SMEM_BYTES>>>(attn_ptr, woutt, out,
                                                         M_ROWS, CC, CC);
    }
}